// round 16
// baseline (speedup 1.0000x reference)
#include <cuda_runtime.h>
#include <cuda_bf16.h>
#include <math.h>

#define Bq   32
#define Lq   512
#define Hq   512
#define DIN  832
#define G3   1536
#define BL   (Bq*Lq)          // 16384

// ------------------------- scratch (device globals) -------------------------
__device__ __align__(16) unsigned short g_X[2][(size_t)BL * DIN];   // bf16, 55 MB
__device__ __align__(16) unsigned short g_w16[2 * G3 * DIN];        // bf16 wih copy
__device__ __align__(16) unsigned short g_gi[4][(size_t)BL * G3];   // bf16, 201 MB
__device__ __align__(16) unsigned short g_h[4][2][Bq * Hq];         // bf16 hidden [b][k]
__device__ __align__(16) unsigned short g_enc[2][(size_t)BL * 1024];// bf16, 67 MB
__device__ __align__(16) float g_sim[(size_t)Bq * Lq * Lq];         // 33.5 MB
__device__ __align__(16) float g_rn[2][BL];                         // 1/row-norm of enc
__device__ __align__(16) float g_max1[BL], g_rel1[BL], g_max2[BL], g_rel2[BL];
__device__ __align__(16) float g_feat[Bq * 768];
__device__ unsigned g_ctr[4];

__device__ __forceinline__ void cpa16(void* dst, const void* src) {
    unsigned d = (unsigned)__cvta_generic_to_shared(dst);
    asm volatile("cp.async.cg.shared.global [%0], [%1], 16;\n" :: "r"(d), "l"(src));
}
__device__ __forceinline__ unsigned short f2b(float x) {
    __nv_bfloat16 v = __float2bfloat16(x);
    return *(unsigned short*)&v;
}
__device__ __forceinline__ float b2f(unsigned short u) {
    __nv_bfloat16 v = *(__nv_bfloat16*)&u;
    return __bfloat162float(v);
}

// ------------------------- init -------------------------
__global__ void k_init() {
    int i = blockIdx.x * blockDim.x + threadIdx.x;
    if (i < 4 * 2 * Bq * Hq) (&g_h[0][0][0])[i] = 0;
    if (i < 4) g_ctr[i] = 0u;
}

// ------------------------- wih -> bf16 copy -------------------------
__global__ void k_cvtw(const float* __restrict__ wih) {
    int i = blockIdx.x * 256 + threadIdx.x;
    g_w16[i] = f2b(wih[i]);
}

// ------------------------- embedding concat (bf16 X) -------------------------
__global__ void k_embed(const int* __restrict__ w1, const int* __restrict__ w2,
                        const int* __restrict__ p1, const int* __restrict__ p2,
                        const int* __restrict__ tb1, const int* __restrict__ te1,
                        const int* __restrict__ tb2, const int* __restrict__ te2,
                        const float* __restrict__ ew, const float* __restrict__ ep,
                        const float* __restrict__ pe) {
    int tok  = blockIdx.x;
    int side = blockIdx.y;
    int t    = tok & (Lq - 1);
    const int* w  = side ? w2  : w1;
    const int* pp = side ? p2  : p1;
    const int* tb = side ? tb2 : tb1;
    const int* te = side ? te2 : te1;
    int wi = w[tok], pi = pp[tok], bi = tb[tok], ei = te[tok];
    unsigned short* dst = g_X[side] + (size_t)tok * DIN;
    const float* s0 = ew + (size_t)wi * 256;
    const float* s1 = ep + (size_t)pi * 256;
    for (int i = threadIdx.x; i < 256; i += 128) {
        dst[i]       = f2b(s0[i]);
        dst[256 + i] = f2b(s1[i]);
    }
    const float* q0 = pe + t * 64;
    const float* q1 = pe + bi * 64;
    const float* q2 = pe + ei * 64;
    const float* q3 = pe + (ei - t) * 64;
    const float* q4 = pe + (t - bi) * 64;
    for (int i = threadIdx.x; i < 64; i += 128) {
        dst[512 + i] = f2b(q0[i]);
        dst[576 + i] = f2b(q1[i]);
        dst[640 + i] = f2b(q2[i]);
        dst[704 + i] = f2b(q3[i]);
        dst[768 + i] = f2b(q4[i]);
    }
}

// ------------------------- bf16 gi GEMM (cp.async 3-stage, m16n8k16) -------------------------
#define NSTG 3
#define BSTR 20
#define G16_SLOT (2 * 128 * BSTR)
#define G16_SMEM (NSTG * G16_SLOT * 4)

__global__ void __launch_bounds__(256, 2) k_gemm16(
    const float* __restrict__ bih,
    const int* __restrict__ len1, const int* __restrict__ len2)
{
    extern __shared__ unsigned smg[];
    int z = blockIdx.z;
    int side = z >> 1, dir = z & 1;
    const unsigned short* A = g_X[side];
    const unsigned short* B = g_w16 + (size_t)dir * G3 * DIN;
    const float* bias = bih + dir * G3;
    unsigned short* C = g_gi[z];
    const int* lens = side ? len2 : len1;
    int tid = threadIdx.x;
    int m0 = blockIdx.y * 128, n0 = blockIdx.x * 128;

    const unsigned short* asrc[2]; const unsigned short* bsrc[2]; int cdst[2];
#pragma unroll
    for (int i = 0; i < 2; i++) {
        int c = tid + 256 * i;
        int row = c >> 2, q = c & 3;
        int ar = m0 + row;
        if (dir) {
            int b = ar >> 9, t = ar & 511;
            int Lb = lens[b];
            ar = (b << 9) + ((t < Lb) ? (Lb - 1 - t) : t);
        }
        asrc[i] = A + (size_t)ar * DIN + q * 8;
        bsrc[i] = B + (size_t)(n0 + row) * DIN + q * 8;
        cdst[i] = row * BSTR + q * 4;
    }

    const int KT = DIN / 32;
#pragma unroll
    for (int s = 0; s < 2; s++) {
        unsigned* As = smg + s * G16_SLOT;
        unsigned* Bs = As + 128 * BSTR;
#pragma unroll
        for (int i = 0; i < 2; i++) {
            cpa16(As + cdst[i], asrc[i] + s * 32);
            cpa16(Bs + cdst[i], bsrc[i] + s * 32);
        }
        asm volatile("cp.async.commit_group;\n");
    }

    int lane = tid & 31, warp = tid >> 5;
    int mbase = (warp & 3) * 32, nbase = (warp >> 2) * 64;

    float c[2][8][4];
#pragma unroll
    for (int i = 0; i < 2; i++)
#pragma unroll
        for (int j = 0; j < 8; j++)
#pragma unroll
            for (int r = 0; r < 4; r++) c[i][j][r] = 0.f;

    for (int kt = 0; kt < KT; kt++) {
        asm volatile("cp.async.wait_group 1;\n");
        __syncthreads();
        const unsigned* Au = smg + (kt % NSTG) * G16_SLOT;
        const unsigned* Bu = Au + 128 * BSTR;
        if (kt + 2 < KT) {
            unsigned* As2 = smg + ((kt + 2) % NSTG) * G16_SLOT;
            unsigned* Bs2 = As2 + 128 * BSTR;
#pragma unroll
            for (int i = 0; i < 2; i++) {
                cpa16(As2 + cdst[i], asrc[i] + (kt + 2) * 32);
                cpa16(Bs2 + cdst[i], bsrc[i] + (kt + 2) * 32);
            }
        }
        asm volatile("cp.async.commit_group;\n");

#pragma unroll
        for (int ks = 0; ks < 2; ks++) {
            int kw = ks * 8 + (lane & 3);
            unsigned a[2][4];
#pragma unroll
            for (int i = 0; i < 2; i++) {
                int ao = (mbase + i * 16 + (lane >> 2)) * BSTR + kw;
                a[i][0] = Au[ao];
                a[i][1] = Au[ao + 8 * BSTR];
                a[i][2] = Au[ao + 4];
                a[i][3] = Au[ao + 8 * BSTR + 4];
            }
#pragma unroll
            for (int j = 0; j < 8; j++) {
                int bo = (nbase + j * 8 + (lane >> 2)) * BSTR + kw;
                unsigned b0 = Bu[bo], b1 = Bu[bo + 4];
#pragma unroll
                for (int i = 0; i < 2; i++) {
                    asm volatile(
                        "mma.sync.aligned.m16n8k16.row.col.f32.bf16.bf16.f32 "
                        "{%0,%1,%2,%3}, {%4,%5,%6,%7}, {%8,%9}, {%0,%1,%2,%3};"
                        : "+f"(c[i][j][0]), "+f"(c[i][j][1]),
                          "+f"(c[i][j][2]), "+f"(c[i][j][3])
                        : "r"(a[i][0]), "r"(a[i][1]), "r"(a[i][2]), "r"(a[i][3]),
                          "r"(b0), "r"(b1));
                }
            }
        }
    }

    int crow = lane >> 2, ccol = (lane & 3) * 2;
#pragma unroll
    for (int i = 0; i < 2; i++) {
#pragma unroll
        for (int j = 0; j < 8; j++) {
            int m = m0 + mbase + i * 16 + crow;
            int n = n0 + nbase + j * 8 + ccol;
            float b0v = bias[n], b1v = bias[n + 1];
            unsigned p0 = (unsigned)f2b(c[i][j][0] + b0v) | ((unsigned)f2b(c[i][j][1] + b1v) << 16);
            unsigned p1 = (unsigned)f2b(c[i][j][2] + b0v) | ((unsigned)f2b(c[i][j][3] + b1v) << 16);
            *(unsigned*)(C + (size_t)m * G3 + n)       = p0;
            *(unsigned*)(C + (size_t)(m + 8) * G3 + n) = p1;
        }
    }
}

// ------------------------- bf16 sim GEMM + cosine epilogue -------------------------
__global__ void __launch_bounds__(256, 2) k_sim16()
{
    extern __shared__ unsigned smg[];
    int z = blockIdx.z;
    const unsigned short* A = g_enc[0] + (size_t)z * Lq * 1024;
    const unsigned short* B = g_enc[1] + (size_t)z * Lq * 1024;
    float* C = g_sim + (size_t)z * Lq * Lq;
    const int K = 1024, N = Lq;
    int tid = threadIdx.x;
    int m0 = blockIdx.y * 128, n0 = blockIdx.x * 128;

    const unsigned short* asrc[2]; const unsigned short* bsrc[2]; int cdst[2];
#pragma unroll
    for (int i = 0; i < 2; i++) {
        int c = tid + 256 * i;
        int row = c >> 2, q = c & 3;
        asrc[i] = A + (size_t)(m0 + row) * K + q * 8;
        bsrc[i] = B + (size_t)(n0 + row) * K + q * 8;
        cdst[i] = row * BSTR + q * 4;
    }

    const int KT = K / 32;
#pragma unroll
    for (int s = 0; s < 2; s++) {
        unsigned* As = smg + s * G16_SLOT;
        unsigned* Bs = As + 128 * BSTR;
#pragma unroll
        for (int i = 0; i < 2; i++) {
            cpa16(As + cdst[i], asrc[i] + s * 32);
            cpa16(Bs + cdst[i], bsrc[i] + s * 32);
        }
        asm volatile("cp.async.commit_group;\n");
    }

    int lane = tid & 31, warp = tid >> 5;
    int mbase = (warp & 3) * 32, nbase = (warp >> 2) * 64;

    float c[2][8][4];
#pragma unroll
    for (int i = 0; i < 2; i++)
#pragma unroll
        for (int j = 0; j < 8; j++)
#pragma unroll
            for (int r = 0; r < 4; r++) c[i][j][r] = 0.f;

    for (int kt = 0; kt < KT; kt++) {
        asm volatile("cp.async.wait_group 1;\n");
        __syncthreads();
        const unsigned* Au = smg + (kt % NSTG) * G16_SLOT;
        const unsigned* Bu = Au + 128 * BSTR;
        if (kt + 2 < KT) {
            unsigned* As2 = smg + ((kt + 2) % NSTG) * G16_SLOT;
            unsigned* Bs2 = As2 + 128 * BSTR;
#pragma unroll
            for (int i = 0; i < 2; i++) {
                cpa16(As2 + cdst[i], asrc[i] + (kt + 2) * 32);
                cpa16(Bs2 + cdst[i], bsrc[i] + (kt + 2) * 32);
            }
        }
        asm volatile("cp.async.commit_group;\n");

#pragma unroll
        for (int ks = 0; ks < 2; ks++) {
            int kw = ks * 8 + (lane & 3);
            unsigned a[2][4];
#pragma unroll
            for (int i = 0; i < 2; i++) {
                int ao = (mbase + i * 16 + (lane >> 2)) * BSTR + kw;
                a[i][0] = Au[ao];
                a[i][1] = Au[ao + 8 * BSTR];
                a[i][2] = Au[ao + 4];
                a[i][3] = Au[ao + 8 * BSTR + 4];
            }
#pragma unroll
            for (int j = 0; j < 8; j++) {
                int bo = (nbase + j * 8 + (lane >> 2)) * BSTR + kw;
                unsigned b0 = Bu[bo], b1 = Bu[bo + 4];
#pragma unroll
                for (int i = 0; i < 2; i++) {
                    asm volatile(
                        "mma.sync.aligned.m16n8k16.row.col.f32.bf16.bf16.f32 "
                        "{%0,%1,%2,%3}, {%4,%5,%6,%7}, {%8,%9}, {%0,%1,%2,%3};"
                        : "+f"(c[i][j][0]), "+f"(c[i][j][1]),
                          "+f"(c[i][j][2]), "+f"(c[i][j][3])
                        : "r"(a[i][0]), "r"(a[i][1]), "r"(a[i][2]), "r"(a[i][3]),
                          "r"(b0), "r"(b1));
                }
            }
        }
    }

    int crow = lane >> 2, ccol = (lane & 3) * 2;
    const float* rn1 = g_rn[0] + z * Lq;
    const float* rn2 = g_rn[1] + z * Lq;
#pragma unroll
    for (int i = 0; i < 2; i++) {
#pragma unroll
        for (int j = 0; j < 8; j++) {
            int m = m0 + mbase + i * 16 + crow;
            int n = n0 + nbase + j * 8 + ccol;
            float sm0 = rn1[m], sm1 = rn1[m + 8];
            float sn0 = rn2[n], sn1 = rn2[n + 1];
            C[(size_t)m * N + n]           = c[i][j][0] * sm0 * sn0;
            C[(size_t)m * N + n + 1]       = c[i][j][1] * sm0 * sn1;
            C[(size_t)(m + 8) * N + n]     = c[i][j][2] * sm1 * sn0;
            C[(size_t)(m + 8) * N + n + 1] = c[i][j][3] * sm1 * sn1;
        }
    }
}

// ------------------------- persistent GRU scan (bf16, 16 blocks/chain, 32 units/block) -------------------------
// gh[96,32] = Ws[96,512] @ h[32,512]^T. Warp = (ks quarter of K, mh half of M).
// part fp32 [4][96*33]; gis coalesced gate-value staging [96][33].
#define HSTR 520
#define GRU_SMEM (96 * HSTR * 2 + 32 * HSTR * 2 + 4 * 96 * 33 * 4 + 96 * 33 * 2)

__global__ void __launch_bounds__(256, 1) k_gru(
    const float* __restrict__ whh, const float* __restrict__ bhh,
    const int* __restrict__ len1, const int* __restrict__ len2)
{
    extern __shared__ unsigned short sm16[];
    unsigned short* Ws16 = sm16;                          // [96][HSTR] bf16
    unsigned short* hT16 = sm16 + 96 * HSTR;              // [32][HSTR] bf16
    float* part = (float*)(sm16 + 96 * HSTR + 32 * HSTR); // [4][96*33] fp32
    unsigned short* gis = (unsigned short*)(part + 4 * 96 * 33); // [96][33] bf16

    int chain = blockIdx.x >> 4;
    int blk   = blockIdx.x & 15;
    int side  = chain >> 1, dir = chain & 1;
    int j0    = blk * 32;
    int tid   = threadIdx.x;
    int lane  = tid & 31, warp = tid >> 5;
    const int* lens = side ? len2 : len1;
    const unsigned short* gi = g_gi[chain];
    unsigned short* enc = g_enc[side];

    // load + convert Whh slice: rr = g*32+u  <->  whh row dir*1536 + g*512 + j0 + u
    for (int i = tid; i < 96 * 512; i += 256) {
        int rr = i >> 9, k = i & 511;
        int g = rr >> 5, u = rr & 31;
        Ws16[rr * HSTR + k] = f2b(whh[((size_t)dir * G3 + g * 512 + j0 + u) * 512 + k]);
    }

    // gate-phase mapping: thread (gb = tid&31 batch, uu = tid>>5), units u = uu + 8q, q=0..3
    int gb = tid & 31;
    int uu = tid >> 5;
    int lenb = lens[gb];
    float bh[3][4];
#pragma unroll
    for (int g = 0; g < 3; g++)
#pragma unroll
        for (int q = 0; q < 4; q++)
            bh[g][q] = bhh[dir * G3 + g * 512 + j0 + uu + 8 * q];

    // coalesced gi staging: e -> (egb = e/96, gate = (e%96)>>5, u2 = e&31)
    int ge[12], gdst[12];
#pragma unroll
    for (int i = 0; i < 12; i++) {
        int e = tid + i * 256;
        int egb = e / 96, rem = e % 96;
        int gate = rem >> 5, u2 = rem & 31;
        ge[i]   = (egb << 9) * G3 + gate * 512 + j0 + u2;
        gdst[i] = (gate * 32 + u2) * 33 + egb;
    }

    int ks4 = warp >> 1;          // K quarter 0..3
    int mh  = warp & 1;           // M half 0..1 (48 rows each)
    int kbase = ks4 << 7;         // *128
    unsigned tgt = 0;

    for (int t = 0; t < Lq; ++t) {
        int p = t & 1;
        const unsigned short* hsrc = g_h[chain][p];
        for (int i = tid; i < 2048; i += 256) {
            uint4 v = __ldcg((const uint4*)(hsrc + i * 8));
            int b = i >> 6, k = (i & 63) * 8;
            *(uint4*)(hT16 + b * HSTR + k) = v;
        }
        {
            const unsigned short* gt = gi + (size_t)t * G3;
#pragma unroll
            for (int i = 0; i < 12; i++)
                gis[gdst[i]] = __ldg(gt + ge[i]);
        }
        __syncthreads();

        // mma: K slice [kbase, kbase+128), M rows [mh*48, mh*48+48)
        float acc[3][4][4];
#pragma unroll
        for (int mt = 0; mt < 3; mt++)
#pragma unroll
            for (int nt = 0; nt < 4; nt++)
#pragma unroll
                for (int r = 0; r < 4; r++) acc[mt][nt][r] = 0.f;

        const unsigned* Wsu = (const unsigned*)Ws16;
        const unsigned* hTu = (const unsigned*)hT16;
#pragma unroll
        for (int ks = 0; ks < 8; ks++) {
            int k0 = kbase + ks * 16;
            int kq = (k0 >> 1) + (lane & 3);
            unsigned a[3][4];
#pragma unroll
            for (int mt = 0; mt < 3; mt++) {
                int ao = (mh * 48 + mt * 16 + (lane >> 2)) * 260 + kq;
                a[mt][0] = Wsu[ao];
                a[mt][1] = Wsu[ao + 8 * 260];
                a[mt][2] = Wsu[ao + 4];
                a[mt][3] = Wsu[ao + 8 * 260 + 4];
            }
            unsigned bfr[4][2];
#pragma unroll
            for (int nt = 0; nt < 4; nt++) {
                int bo = (nt * 8 + (lane >> 2)) * 260 + kq;
                bfr[nt][0] = hTu[bo];
                bfr[nt][1] = hTu[bo + 4];
            }
#pragma unroll
            for (int mt = 0; mt < 3; mt++)
#pragma unroll
                for (int nt = 0; nt < 4; nt++) {
                    asm volatile(
                        "mma.sync.aligned.m16n8k16.row.col.f32.bf16.bf16.f32 "
                        "{%0,%1,%2,%3}, {%4,%5,%6,%7}, {%8,%9}, {%0,%1,%2,%3};"
                        : "+f"(acc[mt][nt][0]), "+f"(acc[mt][nt][1]),
                          "+f"(acc[mt][nt][2]), "+f"(acc[mt][nt][3])
                        : "r"(a[mt][0]), "r"(a[mt][1]), "r"(a[mt][2]), "r"(a[mt][3]),
                          "r"(bfr[nt][0]), "r"(bfr[nt][1]));
                }
        }
        {
            float* pw = part + ks4 * (96 * 33);
            int crow = lane >> 2, ccol = 2 * (lane & 3);
#pragma unroll
            for (int mt = 0; mt < 3; mt++)
#pragma unroll
                for (int nt = 0; nt < 4; nt++) {
                    int r0 = mh * 48 + mt * 16 + crow;
                    int c0 = nt * 8 + ccol;
                    pw[r0 * 33 + c0]           = acc[mt][nt][0];
                    pw[r0 * 33 + c0 + 1]       = acc[mt][nt][1];
                    pw[(r0 + 8) * 33 + c0]     = acc[mt][nt][2];
                    pw[(r0 + 8) * 33 + c0 + 1] = acc[mt][nt][3];
                }
        }
        __syncthreads();

        // reduce 4 K-slices into part[0]
        for (int i = tid; i < 3072; i += 256) {
            int rr = i >> 5, b = i & 31;
            float s = part[rr * 33 + b] + part[96 * 33 + rr * 33 + b]
                    + part[2 * 96 * 33 + rr * 33 + b] + part[3 * 96 * 33 + rr * 33 + b];
            part[rr * 33 + b] = s;
        }
        __syncthreads();

        // gates + h update (4 units per thread); enc stores deferred past publish
        bool valid = t < lenb;
        int tout = dir ? (valid ? lenb - 1 - t : t) : t;
        size_t otok = (size_t)((gb << 9) | tout);
        unsigned short* hdst = g_h[chain][p ^ 1];

        unsigned short eo[4];
#pragma unroll
        for (int q = 0; q < 4; q++) {
            int u = uu + 8 * q;
            float ir = b2f(gis[u * 33 + gb]);
            float iz = b2f(gis[(32 + u) * 33 + gb]);
            float in = b2f(gis[(64 + u) * 33 + gb]);
            unsigned short hpb = hT16[gb * HSTR + j0 + u];
            float hprev = b2f(hpb);
            float hr = part[u * 33 + gb] + bh[0][q];
            float hz = part[(32 + u) * 33 + gb] + bh[1][q];
            float hn = part[(64 + u) * 33 + gb] + bh[2][q];
            float r  = 1.f / (1.f + expf(-(ir + hr)));
            float zz = 1.f / (1.f + expf(-(iz + hz)));
            float nn = tanhf(in + r * hn);
            float hnew = (1.f - zz) * nn + zz * hprev;
            unsigned short hb = f2b(hnew);
            hdst[gb * 512 + j0 + u] = valid ? hb : hpb;
            eo[q] = valid ? hb : 0;
        }

        // publish h(t+1): fence (only h stores in flight), arrive, THEN enc stores
        __threadfence();
        __syncthreads();
        tgt += 16;
        if (tid == 0) atomicAdd(&g_ctr[chain], 1u);
#pragma unroll
        for (int q = 0; q < 4; q++)
            enc[otok * 1024 + (dir << 9) + j0 + uu + 8 * q] = eo[q];
        if (tid == 0) {
            while (*(volatile unsigned*)&g_ctr[chain] < tgt) { }
        }
        __syncthreads();
    }
}

// ------------------------- row inverse-norms of enc (bf16 input) -------------------------
__global__ void k_norm() {
    const unsigned short* row = g_enc[blockIdx.y] + (size_t)blockIdx.x * 1024;
    int tid = threadIdx.x;
    uint4 v = ((const uint4*)row)[tid];
    float ss = 0.f;
    unsigned ws[4] = { v.x, v.y, v.z, v.w };
#pragma unroll
    for (int i = 0; i < 4; i++) {
        float a = b2f((unsigned short)(ws[i] & 0xffff));
        float b = b2f((unsigned short)(ws[i] >> 16));
        ss += a * a + b * b;
    }
    __shared__ float red[4];
    for (int o = 16; o; o >>= 1) ss += __shfl_down_sync(0xffffffffu, ss, o);
    if ((tid & 31) == 0) red[tid >> 5] = ss;
    __syncthreads();
    if (tid == 0) {
        float tot = red[0] + red[1] + red[2] + red[3];
        g_rn[blockIdx.y][blockIdx.x] = tot > 0.f ? rsqrtf(tot) : 0.f;
    }
}

// ------------------------- row / col max+argmax (first-index ties) -------------------------
__global__ void k_rowmax() {
    int row = blockIdx.x * 8 + (threadIdx.x >> 5);
    int l = threadIdx.x & 31;
    const float* s = g_sim + (size_t)row * Lq;
    float bv = -1e30f; int bi = 0;
    for (int j = l; j < Lq; j += 32) {
        float v = s[j];
        if (v > bv) { bv = v; bi = j; }
    }
    for (int o = 16; o; o >>= 1) {
        float ov = __shfl_down_sync(0xffffffffu, bv, o);
        int   oi = __shfl_down_sync(0xffffffffu, bi, o);
        if (ov > bv || (ov == bv && oi < bi)) { bv = ov; bi = oi; }
    }
    if (l == 0) {
        int i = row & 511;
        g_max1[row] = bv;
        g_rel1[row] = (float)(i - bi);
    }
}

__global__ void k_colmax() {
    int id = blockIdx.x * blockDim.x + threadIdx.x;
    int b = id >> 9, j = id & 511;
    const float* s = g_sim + ((size_t)b * Lq) * Lq + j;
    float bv = -1e30f; int bi = 0;
    for (int i = 0; i < Lq; ++i) {
        float v = s[(size_t)i * Lq];
        if (v > bv) { bv = v; bi = i; }
    }
    g_max2[id] = bv;
    g_rel2[id] = (float)(j - bi);
}

// ------------------------- conv branches + maxpool -------------------------
__global__ void k_head(const float* __restrict__ w2p, const float* __restrict__ w3p,
                       const float* __restrict__ w4p, const float* __restrict__ cb,
                       const float* __restrict__ bg, const float* __restrict__ bb,
                       const float* __restrict__ bm, const float* __restrict__ bvv)
{
    int b = blockIdx.x, br = blockIdx.y;
    __shared__ float x0[512], x1[512];
    const float* ms = br ? g_max2 : g_max1;
    const float* rl = br ? g_rel2 : g_rel1;
    for (int i = threadIdx.x; i < 512; i += 128) {
        x0[i] = ms[b * 512 + i];
        x1[i] = rl[b * 512 + i];
    }
    __syncthreads();
    int c = threadIdx.x;
    float* fout = g_feat + b * 768 + br * 384;
    const float* wp[3] = { w2p, w3p, w4p };
    const int kss[3] = { 2, 3, 4 };
    for (int ki = 0; ki < 3; ++ki) {
        int ks = kss[ki];
        float w0[4], w1[4];
        for (int kk = 0; kk < 4; kk++) {
            w0[kk] = kk < ks ? wp[ki][(c * 2 + 0) * ks + kk] : 0.f;
            w1[kk] = kk < ks ? wp[ki][(c * 2 + 1) * ks + kk] : 0.f;
        }
        float s  = bg[ki * 128 + c] / sqrtf(bvv[ki * 128 + c] + 1e-5f);
        float sh = bb[ki * 128 + c] - bm[ki * 128 + c] * s;
        float bias = cb[ki * 128 + c];
        float best = 0.f;
        for (int p = 0; p <= 512 - ks; ++p) {
            float acc = bias;
#pragma unroll
            for (int kk = 0; kk < 4; kk++)
                if (kk < ks) acc += w0[kk] * x0[p + kk] + w1[kk] * x1[p + kk];
            float y = fmaxf(acc * s + sh, 0.f);
            best = fmaxf(best, y);
        }
        fout[ki * 128 + c] = best;
    }
}

// ------------------------- FC + softmax -------------------------
__global__ void k_fc(const float* __restrict__ fcw, const float* __restrict__ fcb,
                     float* __restrict__ out)
{
    int id = threadIdx.x;
    int b = id >> 1, cls = id & 1;
    float acc = fcb[cls];
    const float* f = g_feat + b * 768;
    const float* wrow = fcw + cls * 768;
    for (int k = 0; k < 768; ++k) acc += f[k] * wrow[k];
    float other = __shfl_xor_sync(0xffffffffu, acc, 1);
    float m = fmaxf(acc, other);
    float e = expf(acc - m);
    float ssum = e + expf(other - m);
    out[id] = e / ssum;
}

// ------------------------- launch -------------------------
extern "C" void kernel_launch(void* const* d_in, const int* in_sizes, int n_in,
                              void* d_out, int out_size)
{
    const int* w1  = (const int*)d_in[0];
    const int* w2  = (const int*)d_in[1];
    const int* p1  = (const int*)d_in[2];
    const int* p2  = (const int*)d_in[3];
    const int* ln1 = (const int*)d_in[4];
    const int* ln2 = (const int*)d_in[5];
    const int* tb1 = (const int*)d_in[6];
    const int* te1 = (const int*)d_in[7];
    const int* tb2 = (const int*)d_in[8];
    const int* te2 = (const int*)d_in[9];
    const float* ew   = (const float*)d_in[10];
    const float* ep   = (const float*)d_in[11];
    const float* pe   = (const float*)d_in[12];
    const float* wih  = (const float*)d_in[13];
    const float* whh  = (const float*)d_in[14];
    const float* bih  = (const float*)d_in[15];
    const float* bhh  = (const float*)d_in[16];
    const float* cw0  = (const float*)d_in[17];
    const float* cw1  = (const float*)d_in[18];
    const float* cw2  = (const float*)d_in[19];
    const float* cb   = (const float*)d_in[20];
    const float* bg   = (const float*)d_in[21];
    const float* bb   = (const float*)d_in[22];
    const float* bm   = (const float*)d_in[23];
    const float* bv   = (const float*)d_in[24];
    const float* fcw  = (const float*)d_in[25];
    const float* fcb  = (const float*)d_in[26];
    float* out = (float*)d_out;

    cudaFuncSetAttribute(k_gemm16, cudaFuncAttributeMaxDynamicSharedMemorySize, G16_SMEM);
    cudaFuncSetAttribute(k_sim16, cudaFuncAttributeMaxDynamicSharedMemorySize, G16_SMEM);
    cudaFuncSetAttribute(k_gru, cudaFuncAttributeMaxDynamicSharedMemorySize, GRU_SMEM);

    k_init<<<512, 256>>>();
    k_cvtw<<<2 * G3 * DIN / 256, 256>>>(wih);
    k_embed<<<dim3(BL, 2), 128>>>(w1, w2, p1, p2, tb1, te1, tb2, te2, ew, ep, pe);
    k_gemm16<<<dim3(G3 / 128, BL / 128, 4), 256, G16_SMEM>>>(bih, ln1, ln2);
    k_gru<<<64, 256, GRU_SMEM>>>(whh, bhh, ln1, ln2);
    k_norm<<<dim3(BL, 2), 128>>>();
    k_sim16<<<dim3(Lq / 128, Lq / 128, Bq), 256, G16_SMEM>>>();
    k_rowmax<<<BL / 8, 256>>>();
    k_colmax<<<BL / 256, 256>>>();
    k_head<<<dim3(Bq, 2), 128>>>(cw0, cw1, cw2, cb, bg, bb, bm, bv);
    k_fc<<<1, 64>>>(fcw, fcb, out);
}